// round 3
// baseline (speedup 1.0000x reference)
#include <cuda_runtime.h>
#include <cstdint>
#include <cstddef>

// Problem constants
#define NN 100000
#define EE 400000
#define RR 4
#define NCHUNK 98   // ceil(NN/1024)

// ---------------- scratch (static device globals; no allocation) ----------------
__device__ int   g_deg_in [RR*NN];
__device__ int   g_deg_out[RR*NN];
__device__ int   g_fill   [RR*NN];
__device__ int   g_rowptr [RR*(NN+1)];
__device__ int   g_partial[RR*128];
__device__ int   g_csr    [RR*EE];
__device__ float g_dsin   [RR*NN];
__device__ float g_dsout  [RR*NN];
__device__ float g_h1     [(size_t)NN*128];
__device__ float g_h2     [(size_t)NN*128];
// transposed + bf16-split weights: bt[r][n][k] = W[r][k][n]
__device__ unsigned short g_bt0h[RR*128*128], g_bt0l[RR*128*128];
__device__ unsigned short g_bt1h[RR*128*128], g_bt1l[RR*128*128];
__device__ unsigned short g_bt2h[RR*16*128],  g_bt2l[RR*16*128];

// ---------------- helpers ----------------
__device__ __forceinline__ uint32_t smem_u32(const void* p) {
    uint32_t a;
    asm("{ .reg .u64 t; cvta.to.shared.u64 t, %1; cvt.u32.u64 %0, t; }" : "=r"(a) : "l"(p));
    return a;
}
__device__ __forceinline__ void sts128(uint32_t addr, uint32_t a, uint32_t b, uint32_t c, uint32_t d) {
    asm volatile("st.shared.v4.b32 [%0], {%1,%2,%3,%4};"
                 :: "r"(addr), "r"(a), "r"(b), "r"(c), "r"(d) : "memory");
}
__device__ __forceinline__ void ldsm4(uint32_t* r, uint32_t addr) {
    asm volatile("ldmatrix.sync.aligned.m8n8.x4.shared.b16 {%0,%1,%2,%3}, [%4];"
                 : "=r"(r[0]), "=r"(r[1]), "=r"(r[2]), "=r"(r[3]) : "r"(addr));
}
__device__ __forceinline__ void mma16816(float* d, const uint32_t* a, const uint32_t* b) {
    asm volatile("mma.sync.aligned.m16n8k16.row.col.f32.bf16.bf16.f32 "
                 "{%0,%1,%2,%3}, {%4,%5,%6,%7}, {%8,%9}, {%0,%1,%2,%3};"
                 : "+f"(d[0]), "+f"(d[1]), "+f"(d[2]), "+f"(d[3])
                 : "r"(a[0]), "r"(a[1]), "r"(a[2]), "r"(a[3]), "r"(b[0]), "r"(b[1]));
}
// bf16 round-to-nearest-even (top 16 bits of fp32)
__device__ __forceinline__ uint32_t bfrnd(float f) {
    uint32_t u = __float_as_uint(f);
    return (u + 0x7FFFu + ((u >> 16) & 1u)) >> 16;
}
__device__ __forceinline__ void bfsplit(float f, uint32_t& hb, uint32_t& lb) {
    hb = bfrnd(f);
    float hf = __uint_as_float(hb << 16);
    lb = bfrnd(f - hf);
}

// ---------------- graph preprocessing ----------------
__global__ void zero_counts_kernel() {
    int i = blockIdx.x * blockDim.x + threadIdx.x;
    if (i < RR*NN) { g_deg_in[i] = 0; g_deg_out[i] = 0; g_fill[i] = 0; }
}
__global__ void count_deg_kernel(const int* __restrict__ src, const int* __restrict__ dst) {
    int idx = blockIdx.x * blockDim.x + threadIdx.x;
    if (idx >= RR*EE) return;
    int r = idx / EE;
    atomicAdd(&g_deg_out[r*NN + src[idx]], 1);
    atomicAdd(&g_deg_in [r*NN + dst[idx]], 1);
}
__global__ void scan1_kernel() {
    __shared__ int sh[1024];
    int r = blockIdx.y, c = blockIdx.x;
    int i = c*1024 + threadIdx.x;
    int v = (i < NN) ? g_deg_in[r*NN + i] : 0;
    sh[threadIdx.x] = v;
    __syncthreads();
    for (int off = 1; off < 1024; off <<= 1) {
        int t = (threadIdx.x >= off) ? sh[threadIdx.x - off] : 0;
        __syncthreads();
        sh[threadIdx.x] += t;
        __syncthreads();
    }
    if (i < NN) g_rowptr[r*(NN+1) + i] = sh[threadIdx.x] - v;
    if (threadIdx.x == 1023) g_partial[r*128 + c] = sh[1023];
}
__global__ void scan2_kernel() {
    int r = threadIdx.x;
    if (r >= RR) return;
    int run = 0;
    for (int c = 0; c < NCHUNK; c++) {
        int t = g_partial[r*128 + c];
        g_partial[r*128 + c] = run;
        run += t;
    }
    g_rowptr[r*(NN+1) + NN] = EE;
}
__global__ void scan3_kernel() {
    int r = blockIdx.y, c = blockIdx.x;
    int i = c*1024 + threadIdx.x;
    if (i < NN) g_rowptr[r*(NN+1) + i] += g_partial[r*128 + c];
}
__global__ void fill_csr_kernel(const int* __restrict__ src, const int* __restrict__ dst) {
    int idx = blockIdx.x * blockDim.x + threadIdx.x;
    if (idx >= RR*EE) return;
    int r = idx / EE;
    int d = dst[idx];
    int pos = atomicAdd(&g_fill[r*NN + d], 1);
    g_csr[r*EE + g_rowptr[r*(NN+1) + d] + pos] = src[idx];
}
__global__ void scales_kernel() {
    int i = blockIdx.x * blockDim.x + threadIdx.x;
    if (i >= RR*NN) return;
    g_dsin [i] = rsqrtf((float)max(g_deg_in [i], 1));
    g_dsout[i] = rsqrtf((float)max(g_deg_out[i], 1));
}

// ---------------- weight transpose + bf16 hi/lo split ----------------
__global__ void wsplit_kernel(const float* __restrict__ W0, const float* __restrict__ W1,
                              const float* __restrict__ W2) {
    const int L01 = RR*128*128;      // 65536
    const int L2  = RR*16*128;       // 8192
    int i = blockIdx.x * blockDim.x + threadIdx.x;
    if (i < L01) {
        int r = i >> 14, n = (i >> 7) & 127, k = i & 127;
        uint32_t hb, lb; bfsplit(W0[(r<<14) + k*128 + n], hb, lb);
        g_bt0h[i] = (unsigned short)hb; g_bt0l[i] = (unsigned short)lb;
    } else if (i < 2*L01) {
        int j = i - L01;
        int r = j >> 14, n = (j >> 7) & 127, k = j & 127;
        uint32_t hb, lb; bfsplit(W1[(r<<14) + k*128 + n], hb, lb);
        g_bt1h[j] = (unsigned short)hb; g_bt1l[j] = (unsigned short)lb;
    } else if (i < 2*L01 + L2) {
        int j = i - 2*L01;
        int r = j >> 11, n = (j >> 7) & 15, k = j & 127;
        uint32_t hb, lb; bfsplit(W2[r*2048 + k*16 + n], hb, lb);
        g_bt2h[j] = (unsigned short)hb; g_bt2l[j] = (unsigned short)lb;
    }
}

// ---------------- fused layer: CSR gather -> bf16 split -> mma.sync GEMM -> bias/relu/mean ----------------
// CTA: 128 rows (nodes). For r in 0..3:
//   A_r[row][k] = dsin_r[row] * sum_{e in in(row,r)} h[src_e][k] * dsout_r[src_e]   (bf16 hi/lo in smem)
//   D_r = A_r @ W_r  (3-term bf16 mma.sync, fp32 acc in regs)
//   sum += act(D_r + b_r)
// out[row] = sum / R
#define AST 136                                 // A/B smem element stride (bf16)

template<int DOUT, bool RELU>
__global__ __launch_bounds__(256, 1) void fused_layer_kernel(
        const float* __restrict__ xin, int in_sel,
        const float* __restrict__ bias,
        float* __restrict__ ext_out, int out_sel) {

    constexpr int WX = (DOUT == 128) ? 2 : 1;   // warps along N
    constexpr int MT = (DOUT == 128) ? 2 : 1;   // m16 tiles per warp
    constexpr int NT = (DOUT == 128) ? 8 : 2;   // n8 tiles per warp
    constexpr int A_BYTES = 128 * AST * 2;      // 34816
    constexpr int B_BYTES = DOUT * AST * 2;
    constexpr int OFF_AHI = 2048;
    constexpr int OFF_ALO = OFF_AHI + A_BYTES;
    constexpr int OFF_BHI = OFF_ALO + A_BYTES;
    constexpr int OFF_BLO = OFF_BHI + B_BYTES;

    extern __shared__ char dsm[];
    float* bias_sh = reinterpret_cast<float*>(dsm);
    uint32_t smem_base = smem_u32(dsm);

    int tid  = threadIdx.x;
    int lane = tid & 31;
    int wid  = tid >> 5;
    int m0   = blockIdx.x * 128;

    const float* hsrc = (in_sel == 0) ? xin : ((in_sel == 1) ? g_h1 : g_h2);
    const unsigned short* bth = (in_sel == 0) ? g_bt0h : ((in_sel == 1) ? g_bt1h : g_bt2h);
    const unsigned short* btl = (in_sel == 0) ? g_bt0l : ((in_sel == 1) ? g_bt1l : g_bt2l);
    float* outp = (out_sel == 0) ? g_h1 : ((out_sel == 1) ? g_h2 : ext_out);

    // bias -> smem (once)
    for (int i = tid; i < RR*DOUT; i += 256) bias_sh[i] = bias[i];

    const int n_w = (wid % WX) * NT * 8;
    const int m_w = (wid / WX) * MT * 16;

    float sum[MT][NT][4];
    #pragma unroll
    for (int i = 0; i < MT; i++)
        #pragma unroll
        for (int j = 0; j < NT; j++)
            #pragma unroll
            for (int c = 0; c < 4; c++) sum[i][j][c] = 0.f;

    for (int r = 0; r < RR; r++) {
        __syncthreads();   // protect smem from previous iteration's ldmatrix reads (+ bias on iter 0)

        // ---- gather A_r into smem (bf16 hi/lo) ----
        #pragma unroll
        for (int ig = 0; ig < 4; ig++) {
            int row = ig * 32 + (tid >> 3);
            int c0  = (tid & 7) * 16;
            int n   = m0 + row;
            float acc[16];
            #pragma unroll
            for (int i = 0; i < 16; i++) acc[i] = 0.f;
            if (n < NN) {
                int beg = g_rowptr[r*(NN+1) + n];
                int end = g_rowptr[r*(NN+1) + n + 1];
                for (int e = beg; e < end; e++) {
                    int s   = g_csr[r*EE + e];
                    float w = g_dsout[r*NN + s];
                    const float4* hp = reinterpret_cast<const float4*>(hsrc + (size_t)s*128 + c0);
                    #pragma unroll
                    for (int q = 0; q < 4; q++) {
                        float4 v = hp[q];
                        acc[q*4+0] = fmaf(v.x, w, acc[q*4+0]);
                        acc[q*4+1] = fmaf(v.y, w, acc[q*4+1]);
                        acc[q*4+2] = fmaf(v.z, w, acc[q*4+2]);
                        acc[q*4+3] = fmaf(v.w, w, acc[q*4+3]);
                    }
                }
                float si = g_dsin[r*NN + n];
                #pragma unroll
                for (int i = 0; i < 16; i++) acc[i] *= si;
            }
            uint32_t hp8[8], lp8[8];
            #pragma unroll
            for (int p = 0; p < 8; p++) {
                uint32_t h0, l0, h1, l1;
                bfsplit(acc[2*p+0], h0, l0);
                bfsplit(acc[2*p+1], h1, l1);
                hp8[p] = (h1 << 16) | h0;
                lp8[p] = (l1 << 16) | l0;
            }
            uint32_t off = (uint32_t)(row * AST + c0) * 2;
            sts128(smem_base + OFF_AHI + off,      hp8[0], hp8[1], hp8[2], hp8[3]);
            sts128(smem_base + OFF_AHI + off + 16, hp8[4], hp8[5], hp8[6], hp8[7]);
            sts128(smem_base + OFF_ALO + off,      lp8[0], lp8[1], lp8[2], lp8[3]);
            sts128(smem_base + OFF_ALO + off + 16, lp8[4], lp8[5], lp8[6], lp8[7]);
        }

        // ---- load B_r (pre-split bf16 [n][k]) into smem ----
        if (tid < DOUT * 2) {
            int nrow = tid >> 1;
            int kh   = (tid & 1) * 64;
            const uint4* ph = reinterpret_cast<const uint4*>(bth + ((size_t)r*DOUT + nrow)*128 + kh);
            const uint4* pl = reinterpret_cast<const uint4*>(btl + ((size_t)r*DOUT + nrow)*128 + kh);
            uint32_t off = (uint32_t)(nrow * AST + kh) * 2;
            #pragma unroll
            for (int g = 0; g < 8; g++) {
                uint4 q = ph[g];
                sts128(smem_base + OFF_BHI + off + g*16, q.x, q.y, q.z, q.w);
                q = pl[g];
                sts128(smem_base + OFF_BLO + off + g*16, q.x, q.y, q.z, q.w);
            }
        }
        __syncthreads();

        // ---- 3-term bf16 MMA: D = AhiBhi + AloBhi + AhiBlo ----
        float acc[MT][NT][4];
        #pragma unroll
        for (int i = 0; i < MT; i++)
            #pragma unroll
            for (int j = 0; j < NT; j++)
                #pragma unroll
                for (int c = 0; c < 4; c++) acc[i][j][c] = 0.f;

        const uint32_t aoff[3] = { OFF_AHI, OFF_ALO, OFF_AHI };
        const uint32_t boff[3] = { OFF_BHI, OFF_BHI, OFF_BLO };

        // lane components for ldmatrix addressing
        const int a_r = lane & 15;              // row within 16
        const int a_c = (lane >> 4) << 3;       // 0 or 8 (k-half)
        const int b_q = lane >> 3;
        const int b_n = ((b_q >> 1) << 3) + (lane & 7);   // n within 16
        const int b_c = (b_q & 1) << 3;                   // 0 or 8 (k-half)

        for (int t = 0; t < 3; t++) {
            uint32_t abase = smem_base + aoff[t];
            uint32_t bbase = smem_base + boff[t];
            #pragma unroll
            for (int ks = 0; ks < 8; ks++) {
                int k0 = ks * 16;
                uint32_t a[MT][4];
                #pragma unroll
                for (int i = 0; i < MT; i++)
                    ldsm4(a[i], abase + (uint32_t)((m_w + i*16 + a_r) * AST + k0 + a_c) * 2);
                uint32_t b[NT][2];
                #pragma unroll
                for (int j = 0; j < NT; j += 2) {
                    uint32_t tmp[4];
                    ldsm4(tmp, bbase + (uint32_t)((n_w + j*8 + b_n) * AST + k0 + b_c) * 2);
                    b[j][0] = tmp[0]; b[j][1] = tmp[1];
                    b[j+1][0] = tmp[2]; b[j+1][1] = tmp[3];
                }
                #pragma unroll
                for (int i = 0; i < MT; i++)
                    #pragma unroll
                    for (int j = 0; j < NT; j++)
                        mma16816(acc[i][j], a[i], b[j]);
            }
        }

        // ---- epilogue: sum += act(D + b_r) ----
        #pragma unroll
        for (int i = 0; i < MT; i++) {
            #pragma unroll
            for (int j = 0; j < NT; j++) {
                int col = n_w + j*8 + (lane & 3)*2;
                float b0v = bias_sh[r*DOUT + col];
                float b1v = bias_sh[r*DOUT + col + 1];
                float v0 = acc[i][j][0] + b0v;
                float v1 = acc[i][j][1] + b1v;
                float v2 = acc[i][j][2] + b0v;
                float v3 = acc[i][j][3] + b1v;
                if (RELU) {
                    v0 = fmaxf(v0, 0.f); v1 = fmaxf(v1, 0.f);
                    v2 = fmaxf(v2, 0.f); v3 = fmaxf(v3, 0.f);
                }
                sum[i][j][0] += v0; sum[i][j][1] += v1;
                sum[i][j][2] += v2; sum[i][j][3] += v3;
            }
        }
    }

    // ---- store out = sum / R ----
    #pragma unroll
    for (int i = 0; i < MT; i++) {
        int row0 = m0 + m_w + i*16 + (lane >> 2);
        #pragma unroll
        for (int j = 0; j < NT; j++) {
            int col = n_w + j*8 + (lane & 3)*2;
            if (row0 < NN) {
                float2 o = make_float2(sum[i][j][0]*0.25f, sum[i][j][1]*0.25f);
                *reinterpret_cast<float2*>(&outp[(size_t)row0*DOUT + col]) = o;
            }
            if (row0 + 8 < NN) {
                float2 o = make_float2(sum[i][j][2]*0.25f, sum[i][j][3]*0.25f);
                *reinterpret_cast<float2*>(&outp[(size_t)(row0+8)*DOUT + col]) = o;
            }
        }
    }
}

#define SMEM128 (2048 + 4*34816)                 // 141312
#define SMEM16  (2048 + 2*34816 + 2*(16*AST*2))  // 80384

// ---------------- launch ----------------
extern "C" void kernel_launch(void* const* d_in, const int* in_sizes, int n_in,
                              void* d_out, int out_size) {
    const float* x  = (const float*)d_in[0];
    const float* W0 = (const float*)d_in[1];
    const float* b0 = (const float*)d_in[2];
    const float* W1 = (const float*)d_in[3];
    const float* b1 = (const float*)d_in[4];
    const float* W2 = (const float*)d_in[5];
    const float* b2 = (const float*)d_in[6];
    const int*   src = (const int*)d_in[7];
    const int*   dst = (const int*)d_in[8];
    float* out = (float*)d_out;

    cudaFuncSetAttribute(fused_layer_kernel<128, true >, cudaFuncAttributeMaxDynamicSharedMemorySize, SMEM128);
    cudaFuncSetAttribute(fused_layer_kernel<16,  false>, cudaFuncAttributeMaxDynamicSharedMemorySize, SMEM16);

    // graph preprocessing (once per launch; shared by all 3 layers)
    zero_counts_kernel<<<(RR*NN + 255)/256, 256>>>();
    count_deg_kernel  <<<(RR*EE + 255)/256, 256>>>(src, dst);
    scan1_kernel      <<<dim3(NCHUNK, RR), 1024>>>();
    scan2_kernel      <<<1, RR>>>();
    scan3_kernel      <<<dim3(NCHUNK, RR), 1024>>>();
    fill_csr_kernel   <<<(RR*EE + 255)/256, 256>>>(src, dst);
    scales_kernel     <<<(RR*NN + 255)/256, 256>>>();
    wsplit_kernel     <<<(2*RR*128*128 + RR*16*128 + 255)/256, 256>>>(W0, W1, W2);

    const int MB = (NN + 127) / 128;   // 782 CTAs

    fused_layer_kernel<128, true ><<<MB, 256, SMEM128>>>(x,       0, b0, nullptr, 0);
    fused_layer_kernel<128, true ><<<MB, 256, SMEM128>>>(nullptr, 1, b1, nullptr, 1);
    fused_layer_kernel<16,  false><<<MB, 256, SMEM16 >>>(nullptr, 2, b2, out,     2);
}

// round 4
// speedup vs baseline: 1.6931x; 1.6931x over previous
#include <cuda_runtime.h>
#include <cstdint>
#include <cstddef>

// Problem constants
#define NN 100000
#define NPAD 100096   // 782 * 128
#define EE 400000
#define RR 4
#define NCHUNK 98     // ceil(NN/1024)

// ---------------- scratch (static device globals; no allocation) ----------------
__device__ int   g_deg_in [RR*NN];
__device__ int   g_deg_out[RR*NN];
__device__ int   g_fill   [RR*NN];
__device__ int   g_rowptr [RR*(NN+1)];
__device__ int   g_partial[RR*128];
__device__ int   g_csr    [RR*EE];
__device__ float g_dsin   [RR*NN];
__device__ float g_dsout  [RR*NN];
__device__ float g_h1     [(size_t)NPAD*128];
__device__ float g_y2     [(size_t)NN*64];
// aggregated features, pre-split bf16 hi/lo: [R][NPAD][128]  (pad rows stay zero)
__device__ __align__(16) unsigned short g_aggh[(size_t)RR*NPAD*128];
__device__ __align__(16) unsigned short g_aggl[(size_t)RR*NPAD*128];
// layer-1 output, pre-split bf16 hi/lo: [NPAD][128]
__device__ __align__(16) unsigned short g_h2h[(size_t)NPAD*128];
__device__ __align__(16) unsigned short g_h2l[(size_t)NPAD*128];
// transposed + bf16-split weights: bt[r][n][k] = W[r][k][n]
__device__ __align__(16) unsigned short g_bt0h[RR*128*128], g_bt0l[RR*128*128];
__device__ __align__(16) unsigned short g_bt1h[RR*128*128], g_bt1l[RR*128*128];
__device__ __align__(16) unsigned short g_bt2h[64*128],     g_bt2l[64*128];   // [r*16+n][k]

// ---------------- helpers ----------------
__device__ __forceinline__ uint32_t smem_u32(const void* p) {
    uint32_t a;
    asm("{ .reg .u64 t; cvta.to.shared.u64 t, %1; cvt.u32.u64 %0, t; }" : "=r"(a) : "l"(p));
    return a;
}
__device__ __forceinline__ void ldsm4(uint32_t* r, uint32_t addr) {
    asm volatile("ldmatrix.sync.aligned.m8n8.x4.shared.b16 {%0,%1,%2,%3}, [%4];"
                 : "=r"(r[0]), "=r"(r[1]), "=r"(r[2]), "=r"(r[3]) : "r"(addr));
}
__device__ __forceinline__ void mma16816(float* d, const uint32_t* a, const uint32_t* b) {
    asm volatile("mma.sync.aligned.m16n8k16.row.col.f32.bf16.bf16.f32 "
                 "{%0,%1,%2,%3}, {%4,%5,%6,%7}, {%8,%9}, {%0,%1,%2,%3};"
                 : "+f"(d[0]), "+f"(d[1]), "+f"(d[2]), "+f"(d[3])
                 : "r"(a[0]), "r"(a[1]), "r"(a[2]), "r"(a[3]), "r"(b[0]), "r"(b[1]));
}
__device__ __forceinline__ void cp16(uint32_t dst, const void* src) {
    asm volatile("cp.async.cg.shared.global [%0], [%1], 16;" :: "r"(dst), "l"(src));
}
#define CP_COMMIT() asm volatile("cp.async.commit_group;" ::: "memory")
#define CP_WAIT(n)  asm volatile("cp.async.wait_group " #n ";" ::: "memory")

// bf16 round-to-nearest-even (top 16 bits of fp32)
__device__ __forceinline__ uint32_t bfrnd(float f) {
    uint32_t u = __float_as_uint(f);
    return (u + 0x7FFFu + ((u >> 16) & 1u)) >> 16;
}
__device__ __forceinline__ void bfsplit(float f, uint32_t& hb, uint32_t& lb) {
    hb = bfrnd(f);
    float hf = __uint_as_float(hb << 16);
    lb = bfrnd(f - hf);
}

// ---------------- prep kernels ----------------
__global__ void zero_wsplit_kernel(const float* __restrict__ W0, const float* __restrict__ W1,
                                   const float* __restrict__ W2) {
    int i = blockIdx.x * blockDim.x + threadIdx.x;
    if (i < RR*NN) { g_deg_in[i] = 0; g_deg_out[i] = 0; g_fill[i] = 0; }
    const int L01 = RR*128*128;   // 65536
    if (i < L01) {
        int r = i >> 14, n = (i >> 7) & 127, k = i & 127;
        uint32_t hb, lb; bfsplit(W0[(r<<14) + k*128 + n], hb, lb);
        g_bt0h[i] = (unsigned short)hb; g_bt0l[i] = (unsigned short)lb;
    } else if (i < 2*L01) {
        int j = i - L01;
        int r = j >> 14, n = (j >> 7) & 127, k = j & 127;
        uint32_t hb, lb; bfsplit(W1[(r<<14) + k*128 + n], hb, lb);
        g_bt1h[j] = (unsigned short)hb; g_bt1l[j] = (unsigned short)lb;
    } else if (i < 2*L01 + 64*128) {
        int j = i - 2*L01;
        int r = j >> 11, n = (j >> 7) & 15, k = j & 127;
        uint32_t hb, lb; bfsplit(W2[r*2048 + k*16 + n], hb, lb);
        g_bt2h[j] = (unsigned short)hb; g_bt2l[j] = (unsigned short)lb;
    }
}
__global__ void count_deg_kernel(const int* __restrict__ src, const int* __restrict__ dst) {
    int idx = blockIdx.x * blockDim.x + threadIdx.x;
    if (idx >= RR*EE) return;
    int r = idx / EE;
    atomicAdd(&g_deg_out[r*NN + src[idx]], 1);
    atomicAdd(&g_deg_in [r*NN + dst[idx]], 1);
}
__global__ void scan1_kernel() {
    __shared__ int sh[1024];
    int r = blockIdx.y, c = blockIdx.x;
    int i = c*1024 + threadIdx.x;
    int v = (i < NN) ? g_deg_in[r*NN + i] : 0;
    sh[threadIdx.x] = v;
    __syncthreads();
    for (int off = 1; off < 1024; off <<= 1) {
        int t = (threadIdx.x >= off) ? sh[threadIdx.x - off] : 0;
        __syncthreads();
        sh[threadIdx.x] += t;
        __syncthreads();
    }
    if (i < NN) g_rowptr[r*(NN+1) + i] = sh[threadIdx.x] - v;
    if (threadIdx.x == 1023) g_partial[r*128 + c] = sh[1023];
}
__global__ void scan2_kernel() {
    int r = threadIdx.x;
    if (r >= RR) return;
    int run = 0;
    for (int c = 0; c < NCHUNK; c++) {
        int t = g_partial[r*128 + c];
        g_partial[r*128 + c] = run;
        run += t;
    }
    g_rowptr[r*(NN+1) + NN] = EE;
}
__global__ void scan3_scales_kernel() {
    int r = blockIdx.y, c = blockIdx.x;
    int i = c*1024 + threadIdx.x;
    if (i < NN) {
        g_rowptr[r*(NN+1) + i] += g_partial[r*128 + c];
        int ii = r*NN + i;
        g_dsin [ii] = rsqrtf((float)max(g_deg_in [ii], 1));
        g_dsout[ii] = rsqrtf((float)max(g_deg_out[ii], 1));
    }
}
__global__ void fill_csr_kernel(const int* __restrict__ src, const int* __restrict__ dst) {
    int idx = blockIdx.x * blockDim.x + threadIdx.x;
    if (idx >= RR*EE) return;
    int r = idx / EE;
    int d = dst[idx];
    int pos = atomicAdd(&g_fill[r*NN + d], 1);
    g_csr[r*EE + g_rowptr[r*(NN+1) + d] + pos] = src[idx];
}

// ---------------- gather: agg[r][n] = dsin * sum h[s]*dsout[s]  -> bf16 hi/lo ----------------
__global__ __launch_bounds__(256) void gather_kernel(const float* __restrict__ xin, int use_x) {
    int gw   = (blockIdx.x * blockDim.x + threadIdx.x) >> 5;
    int lane = threadIdx.x & 31;
    if (gw >= RR*NN) return;
    int r = gw / NN, n = gw - r*NN;
    const float* h = use_x ? xin : g_h1;
    int beg = g_rowptr[r*(NN+1) + n];
    int end = g_rowptr[r*(NN+1) + n + 1];
    float4 acc = make_float4(0.f, 0.f, 0.f, 0.f);
    for (int e = beg; e < end; e++) {
        int s = g_csr[r*EE + e];
        float w = g_dsout[r*NN + s];
        float4 v = *reinterpret_cast<const float4*>(&h[(size_t)s*128 + lane*4]);
        acc.x = fmaf(v.x, w, acc.x);
        acc.y = fmaf(v.y, w, acc.y);
        acc.z = fmaf(v.z, w, acc.z);
        acc.w = fmaf(v.w, w, acc.w);
    }
    float si = g_dsin[r*NN + n];
    float vv[4] = { acc.x*si, acc.y*si, acc.z*si, acc.w*si };
    uint32_t h0,l0,h1,l1,h2,l2,h3,l3;
    bfsplit(vv[0], h0, l0); bfsplit(vv[1], h1, l1);
    bfsplit(vv[2], h2, l2); bfsplit(vv[3], h3, l3);
    size_t off = ((size_t)r*NPAD + n)*128 + lane*4;
    *reinterpret_cast<uint2*>(&g_aggh[off]) = make_uint2(h0 | (h1<<16), h2 | (h3<<16));
    *reinterpret_cast<uint2*>(&g_aggl[off]) = make_uint2(l0 | (l1<<16), l2 | (l3<<16));
}

// ---------------- pipelined bf16 3-term GEMM ----------------
// LAYER 0: agg @ W0, +b0, relu, mean -> g_h1 (fp32)
// LAYER 1: agg @ W1, +b1, relu, mean -> g_h2h/g_h2l (bf16 split)
// LAYER 2: h2  @ W2cat (64 cols)      -> g_y2 (fp32, raw)
// CTA: 128 rows x 64 cols. Stages = NREL*4 K-chunks of 32, 2-buffer cp.async ring.
// smem stage: Ah[128][40] Al[128][40] Bh[64][40] Bl[64][40] bf16 = 30720 B; 2 stages = 61440.
#define STAGE_B 30720
#define GEMM_SMEM 61440

template<int LAYER>
__global__ __launch_bounds__(256, 2) void gemm_kernel(const float* __restrict__ bias,
                                                      float* __restrict__ /*unused*/ uext) {
    constexpr int NREL = (LAYER == 2) ? 1 : 4;
    constexpr int S = NREL * 4;

    const unsigned short* Ah = (LAYER == 2) ? g_h2h : g_aggh;
    const unsigned short* Al = (LAYER == 2) ? g_h2l : g_aggl;
    const unsigned short* Bh = (LAYER == 0) ? g_bt0h : ((LAYER == 1) ? g_bt1h : g_bt2h);
    const unsigned short* Bl = (LAYER == 0) ? g_bt0l : ((LAYER == 1) ? g_bt1l : g_bt2l);

    extern __shared__ char dsm[];
    const uint32_t smem_base = smem_u32(dsm);

    const int tid  = threadIdx.x;
    const int lane = tid & 31;
    const int wid  = tid >> 5;
    const int m0   = blockIdx.x * 128;
    const int colBase = blockIdx.y * 64;

    const int m_w = (wid >> 1) * 32;
    const int n_w = (wid & 1) * 32;
    const int a_r = lane & 15;
    const int a_c = (lane >> 4) << 3;
    const int b_q = lane >> 3;
    const int b_n = ((b_q >> 1) << 3) + (lane & 7);
    const int b_c = (b_q & 1) << 3;

    auto load_stage = [&](int s) {
        int r = s >> 2, kc = s & 3;
        uint32_t sb = smem_base + (s & 1) * STAGE_B;
        size_t a_base = ((size_t)r * NPAD + m0) * 128 + kc * 32;
        size_t b_base = ((size_t)(r * 128 + colBase)) * 128 + kc * 32;
        #pragma unroll
        for (int i = 0; i < 6; i++) {
            int g = tid + i * 256;
            if (g < 1024) {
                int arr = g >> 9, idx = g & 511, row = idx >> 2, ch = idx & 3;
                const unsigned short* src = (arr ? Al : Ah) + a_base + (size_t)row * 128 + ch * 8;
                cp16(sb + arr * 10240 + row * 80 + ch * 16, src);
            } else {
                int g2 = g - 1024;
                int arr = g2 >> 8, idx = g2 & 255, row = idx >> 2, ch = idx & 3;
                const unsigned short* src = (arr ? Bl : Bh) + b_base + (size_t)row * 128 + ch * 8;
                cp16(sb + 20480 + arr * 5120 + row * 80 + ch * 16, src);
            }
        }
        CP_COMMIT();
    };

    float acc[2][4][4];
    float sum[2][4][4];
    #pragma unroll
    for (int i = 0; i < 2; i++)
        #pragma unroll
        for (int j = 0; j < 4; j++)
            #pragma unroll
            for (int c = 0; c < 4; c++) { acc[i][j][c] = 0.f; sum[i][j][c] = 0.f; }

    load_stage(0);

    for (int s = 0; s < S; s++) {
        if (s + 1 < S) { load_stage(s + 1); CP_WAIT(1); }
        else           { CP_WAIT(0); }
        __syncthreads();

        uint32_t sb = smem_base + (s & 1) * STAGE_B;
        #pragma unroll
        for (int t = 0; t < 3; t++) {
            uint32_t ab = sb + ((t == 1) ? 10240 : 0);
            uint32_t bb = sb + 20480 + ((t == 2) ? 5120 : 0);
            #pragma unroll
            for (int ks = 0; ks < 2; ks++) {
                int k0 = ks * 16;
                uint32_t a[2][4];
                #pragma unroll
                for (int i = 0; i < 2; i++)
                    ldsm4(a[i], ab + (uint32_t)((m_w + i*16 + a_r) * 40 + k0 + a_c) * 2);
                uint32_t b[4][2];
                #pragma unroll
                for (int jj = 0; jj < 2; jj++) {
                    uint32_t tmp[4];
                    ldsm4(tmp, bb + (uint32_t)((n_w + jj*16 + b_n) * 40 + k0 + b_c) * 2);
                    b[jj*2][0] = tmp[0]; b[jj*2][1] = tmp[1];
                    b[jj*2+1][0] = tmp[2]; b[jj*2+1][1] = tmp[3];
                }
                #pragma unroll
                for (int i = 0; i < 2; i++)
                    #pragma unroll
                    for (int j = 0; j < 4; j++)
                        mma16816(acc[i][j], a[i], b[j]);
            }
        }

        if ((s & 3) == 3) {   // finished relation r = s>>2: fold into sum
            int rr = s >> 2;
            #pragma unroll
            for (int i = 0; i < 2; i++) {
                #pragma unroll
                for (int j = 0; j < 4; j++) {
                    float v0 = acc[i][j][0], v1 = acc[i][j][1];
                    float v2 = acc[i][j][2], v3 = acc[i][j][3];
                    if (LAYER != 2) {
                        int col = colBase + n_w + j*8 + (lane & 3)*2;
                        float b0v = bias[rr*128 + col];
                        float b1v = bias[rr*128 + col + 1];
                        v0 = fmaxf(v0 + b0v, 0.f); v1 = fmaxf(v1 + b1v, 0.f);
                        v2 = fmaxf(v2 + b0v, 0.f); v3 = fmaxf(v3 + b1v, 0.f);
                    }
                    sum[i][j][0] += v0; sum[i][j][1] += v1;
                    sum[i][j][2] += v2; sum[i][j][3] += v3;
                    acc[i][j][0] = 0.f; acc[i][j][1] = 0.f;
                    acc[i][j][2] = 0.f; acc[i][j][3] = 0.f;
                }
            }
        }
        __syncthreads();
    }

    // ---- store ----
    const float scale = (LAYER == 2) ? 1.0f : 0.25f;
    #pragma unroll
    for (int i = 0; i < 2; i++) {
        int row0 = m0 + m_w + i*16 + (lane >> 2);
        #pragma unroll
        for (int j = 0; j < 4; j++) {
            int col = colBase + n_w + j*8 + (lane & 3)*2;
            float p0 = sum[i][j][0]*scale, p1 = sum[i][j][1]*scale;
            float p2 = sum[i][j][2]*scale, p3 = sum[i][j][3]*scale;
            if (LAYER == 0) {
                if (row0 < NN)
                    *reinterpret_cast<float2*>(&g_h1[(size_t)row0*128 + col]) = make_float2(p0, p1);
                if (row0 + 8 < NN)
                    *reinterpret_cast<float2*>(&g_h1[(size_t)(row0+8)*128 + col]) = make_float2(p2, p3);
            } else if (LAYER == 1) {
                uint32_t h0,l0,h1,l1;
                if (row0 < NN) {
                    bfsplit(p0, h0, l0); bfsplit(p1, h1, l1);
                    *reinterpret_cast<uint32_t*>(&g_h2h[(size_t)row0*128 + col]) = h0 | (h1<<16);
                    *reinterpret_cast<uint32_t*>(&g_h2l[(size_t)row0*128 + col]) = l0 | (l1<<16);
                }
                if (row0 + 8 < NN) {
                    bfsplit(p2, h0, l0); bfsplit(p3, h1, l1);
                    *reinterpret_cast<uint32_t*>(&g_h2h[(size_t)(row0+8)*128 + col]) = h0 | (h1<<16);
                    *reinterpret_cast<uint32_t*>(&g_h2l[(size_t)(row0+8)*128 + col]) = l0 | (l1<<16);
                }
            } else {
                if (row0 < NN)
                    *reinterpret_cast<float2*>(&g_y2[(size_t)row0*64 + col]) = make_float2(p0, p1);
                if (row0 + 8 < NN)
                    *reinterpret_cast<float2*>(&g_y2[(size_t)(row0+8)*64 + col]) = make_float2(p2, p3);
            }
        }
    }
}

// ---------------- layer-2 gather: out[n,c] = 0.25 * sum_r (dsin*sum_e y2[s, r*16+c]*dsout + b2[r,c]) ----------------
__global__ __launch_bounds__(256) void gather2_kernel(const float* __restrict__ b2,
                                                      float* __restrict__ out) {
    int gw   = (blockIdx.x * blockDim.x + threadIdx.x) >> 5;
    int lane = threadIdx.x & 31;
    int node = gw * 2 + (lane >> 4);
    int c    = lane & 15;
    if (node >= NN) return;
    float sum = 0.f;
    #pragma unroll
    for (int r = 0; r < RR; r++) {
        int beg = g_rowptr[r*(NN+1) + node];
        int end = g_rowptr[r*(NN+1) + node + 1];
        float acc = 0.f;
        for (int e = beg; e < end; e++) {
            int s = g_csr[r*EE + e];
            acc = fmaf(g_y2[(size_t)s*64 + r*16 + c], g_dsout[r*NN + s], acc);
        }
        sum += g_dsin[r*NN + node] * acc + b2[r*16 + c];
    }
    out[node*16 + c] = 0.25f * sum;
}

// ---------------- launch ----------------
extern "C" void kernel_launch(void* const* d_in, const int* in_sizes, int n_in,
                              void* d_out, int out_size) {
    const float* x  = (const float*)d_in[0];
    const float* W0 = (const float*)d_in[1];
    const float* b0 = (const float*)d_in[2];
    const float* W1 = (const float*)d_in[3];
    const float* b1 = (const float*)d_in[4];
    const float* W2 = (const float*)d_in[5];
    const float* b2 = (const float*)d_in[6];
    const int*   src = (const int*)d_in[7];
    const int*   dst = (const int*)d_in[8];
    float* out = (float*)d_out;

    cudaFuncSetAttribute(gemm_kernel<0>, cudaFuncAttributeMaxDynamicSharedMemorySize, GEMM_SMEM);
    cudaFuncSetAttribute(gemm_kernel<1>, cudaFuncAttributeMaxDynamicSharedMemorySize, GEMM_SMEM);
    cudaFuncSetAttribute(gemm_kernel<2>, cudaFuncAttributeMaxDynamicSharedMemorySize, GEMM_SMEM);

    // prep (shared by all layers)
    zero_wsplit_kernel<<<(RR*NN + 255)/256, 256>>>(W0, W1, W2);
    count_deg_kernel  <<<(RR*EE + 255)/256, 256>>>(src, dst);
    scan1_kernel      <<<dim3(NCHUNK, RR), 1024>>>();
    scan2_kernel      <<<1, RR>>>();
    scan3_scales_kernel<<<dim3(NCHUNK, RR), 1024>>>();
    fill_csr_kernel   <<<(RR*EE + 255)/256, 256>>>(src, dst);

    const int GATHER_BLOCKS = (RR*NN*32 + 255) / 256;  // 50000

    // layer 0: gather(x) -> agg(split) ; gemm -> h1 fp32
    gather_kernel<<<GATHER_BLOCKS, 256>>>(x, 1);
    gemm_kernel<0><<<dim3(782, 2), 256, GEMM_SMEM>>>(b0, nullptr);
    // layer 1: gather(h1) -> agg ; gemm -> h2 bf16-split
    gather_kernel<<<GATHER_BLOCKS, 256>>>(nullptr, 0);
    gemm_kernel<1><<<dim3(782, 2), 256, GEMM_SMEM>>>(b1, nullptr);
    // layer 2 (GEMM-first): y2 = h2 @ W2cat ; tiny gather with bias+mean
    gemm_kernel<2><<<dim3(782, 1), 256, GEMM_SMEM>>>(nullptr, nullptr);
    gather2_kernel<<<(NN/2*32 + 255)/256, 256>>>(b2, out);
}